// round 5
// baseline (speedup 1.0000x reference)
#include <cuda_runtime.h>

#define S_MAX 200000
#define N_MAX 250000
#define LB 64           // L == B == 64
#define ZCHUNK 512

// ---- device scratch (no allocations allowed) ----
__device__ float g_xT[(size_t)N_MAX * LB];    // x transposed [N,64]
__device__ float g_xagg[(size_t)S_MAX * LB];  // aggregated+scaled x per master [S,64]
__device__ float g_yT[(size_t)S_MAX * LB];    // y transposed [S,64]
__device__ float g_z[LB * LB];                // z stored l-major: z[l][b]
__device__ int   g_cm[S_MAX];                 // # added new nodes per master
__device__ int   g_cnt[N_MAX];                // # masters mapping to n
__device__ float g_bdacc[N_MAX];              // segment sum of bd_m
__device__ unsigned char g_added[N_MAX];
// CSR A: master m -> added new nodes n
__device__ int   g_offA[S_MAX];
__device__ int   g_fillA[S_MAX];
__device__ int   g_idxA[N_MAX];
// CSR Y: new node n -> masters m
__device__ int   g_offY[N_MAX];
__device__ int   g_fillY[N_MAX];
__device__ int   g_idxY[S_MAX];
// scan temporaries
__device__ int   g_bsumA[1024];
__device__ int   g_boffA[1024];
__device__ int   g_bsumB[1024];
__device__ int   g_boffB[1024];

// packed f32x2 helpers (SASS FFMA2 — only reachable via PTX)
#define FMA2(d, a, b) asm("fma.rn.f32x2 %0, %1, %2, %0;" : "+l"(d) : "l"(a), "l"(b))
#define PACKB(d, f)   asm("mov.b64 %0, {%1, %1};" : "=l"(d) : "f"(f))
#define UNPACK2(lo, hi, v) asm("mov.b64 {%0, %1}, %2;" : "=f"(lo), "=f"(hi) : "l"(v))

// ---------------- prep: clear everything + z bias ----------------
__global__ void k_prep(const float* __restrict__ be, int S, int N) {
    int i = blockIdx.x * blockDim.x + threadIdx.x;
    if (i < S) { g_cm[i] = 0; g_fillA[i] = 0; }
    if (i < N) { g_cnt[i] = 0; g_bdacc[i] = 0.f; g_fillY[i] = 0; }
    if (i < LB * LB) g_z[i] = be[i >> 6];     // z[l][b] = be[l]
}

// ---------------- stats: added flags + c_m + cnt + bdacc ----------------
__global__ void k_stats(const int* __restrict__ nn_n, const int* __restrict__ nn_m,
                        const float* __restrict__ bd, int S, int N) {
    int i = blockIdx.x * blockDim.x + threadIdx.x;
    if (i < N) {
        int m = nn_n[i];
        int a = (nn_m[m] != i) ? 1 : 0;
        g_added[i] = (unsigned char)a;
        if (a) atomicAdd(&g_cm[m], 1);
    }
    if (i < S) {
        int nm = nn_m[i];
        atomicAdd(&g_cnt[nm], 1);
        atomicAdd(&g_bdacc[nm], bd[i]);
    }
}

// ---------------- x transpose [64,N] -> [N,64] ----------------
__global__ void k_xT(const float* __restrict__ x, int N) {
    __shared__ float tile[32][33];
    int n0 = blockIdx.x * 32;
    int b0 = blockIdx.y * 32;
    int tx = threadIdx.x, ty = threadIdx.y;   // 32 x 8
    #pragma unroll
    for (int i = 0; i < 32; i += 8) {
        int n = n0 + tx;
        tile[ty + i][tx] = (n < N) ? x[(size_t)(b0 + ty + i) * N + n] : 0.f;
    }
    __syncthreads();
    #pragma unroll
    for (int i = 0; i < 32; i += 8) {
        int n = n0 + ty + i;
        if (n < N) g_xT[(size_t)n * LB + b0 + tx] = tile[tx][ty + i];
    }
}

// ---------------- dual 2-level exclusive scans: cm (S) and cnt (N) ----------------
__global__ void k_scan1(int S, int N, int cA) {
    __shared__ int sd[256];
    int t = threadIdx.x;
    int blk = blockIdx.x;
    const int* src; int len; int cbase;
    if (blk < cA) { src = g_cm; len = S; cbase = blk; }
    else          { src = g_cnt; len = N; cbase = blk - cA; }
    int n = cbase * 256 + t;
    sd[t] = (n < len) ? src[n] : 0;
    __syncthreads();
    #pragma unroll
    for (int d = 128; d > 0; d >>= 1) {
        if (t < d) sd[t] += sd[t + d];
        __syncthreads();
    }
    if (t == 0) {
        if (blk < cA) g_bsumA[cbase] = sd[0];
        else          g_bsumB[cbase] = sd[0];
    }
}

__global__ void k_scan2(int cA, int cB) {
    __shared__ int sd[1024];
    int t = threadIdx.x;
    const int* in  = (blockIdx.x == 0) ? g_bsumA : g_bsumB;
    int*       outp = (blockIdx.x == 0) ? g_boffA : g_boffB;
    int nch = (blockIdx.x == 0) ? cA : cB;
    int v = (t < nch) ? in[t] : 0;
    sd[t] = v;
    __syncthreads();
    #pragma unroll
    for (int d = 1; d < 1024; d <<= 1) {
        int add = (t >= d) ? sd[t - d] : 0;
        __syncthreads();
        sd[t] += add;
        __syncthreads();
    }
    if (t < nch) outp[t] = sd[t] - v;   // exclusive
}

__global__ void k_scan3(int S, int N, int cA) {
    __shared__ int sd[256];
    int t = threadIdx.x;
    int blk = blockIdx.x;
    const int* src; int len; int cbase; const int* boff; int* dst;
    if (blk < cA) { src = g_cm;  len = S; cbase = blk;      boff = g_boffA; dst = g_offA; }
    else          { src = g_cnt; len = N; cbase = blk - cA; boff = g_boffB; dst = g_offY; }
    int n = cbase * 256 + t;
    int v = (n < len) ? src[n] : 0;
    sd[t] = v;
    __syncthreads();
    #pragma unroll
    for (int d = 1; d < 256; d <<= 1) {
        int add = (t >= d) ? sd[t - d] : 0;
        __syncthreads();
        sd[t] += add;
        __syncthreads();
    }
    if (n < len) dst[n] = boff[cbase] + sd[t] - v;  // exclusive
}

// ---------------- CSR index fills (both) ----------------
__global__ void k_fill(const int* __restrict__ nn_n, const int* __restrict__ nn_m,
                       int S, int N) {
    int i = blockIdx.x * blockDim.x + threadIdx.x;
    if (i < N && g_added[i]) {
        int m = nn_n[i];
        int pos = g_offA[m] + atomicAdd(&g_fillA[m], 1);
        g_idxA[pos] = i;
    }
    if (i < S) {
        int nm = nn_m[i];
        int pos = g_offY[nm] + atomicAdd(&g_fillY[nm], 1);
        g_idxY[pos] = i;
    }
}

// ---------------- Xagg[m] = scale[m] * ( xT[nn_m[m]] + sum added rows ) ----------------
__global__ void __launch_bounds__(256) k_xagg(const int* __restrict__ nn_m, int S) {
    int w = (blockIdx.x * blockDim.x + threadIdx.x) >> 5;
    int lane = threadIdx.x & 31;
    if (w >= S) return;
    int cm = g_cm[w];
    float scale = 1.0f / (float)(cm + 1);
    const float* base = g_xT + (size_t)nn_m[w] * 64 + lane * 2;
    float2 acc = *(const float2*)base;
    int o = g_offA[w];
    for (int s = 0; s < cm; s++) {
        int n = g_idxA[o + s];
        float2 v = *(const float2*)(g_xT + (size_t)n * 64 + lane * 2);
        acc.x += v.x; acc.y += v.y;
    }
    acc.x *= scale; acc.y *= scale;
    *(float2*)(g_xagg + (size_t)w * 64 + lane * 2) = acc;
}

// ---------------- z GEMM: streaming, 4-way K-split, 8x8 tiles, FFMA2 ----------------
// SB layout: [0..2047] x double-buffer (2 x 16 x 64), [2048..4095] w double-buffer.
// Reduction phase reuses all 4096 floats as the 64x64 partial-z tile.
__global__ void __launch_bounds__(256) k_z(const float* __restrict__ We, int S) {
    __shared__ __align__(16) float SB[4096];
    int tid = threadIdx.x;
    int row = tid >> 4;                      // staging row 0..15
    int col4 = (tid & 15) * 4;               // staging col (float4)
    int t = tid & 63;
    int kg = tid >> 6;                       // k-subgroup 0..3
    int tb = (t & 7) * 8;                    // b-octet base
    int tl = (t >> 3) * 8;                   // l-octet base

    unsigned long long acc[4][8];            // [b-pair][l]
    #pragma unroll
    for (int p = 0; p < 4; p++)
        #pragma unroll
        for (int j = 0; j < 8; j++) acc[p][j] = 0ULL;

    int k0 = blockIdx.x * ZCHUNK;

    // prefetch slab 0
    {
        int k = k0 + row;
        float4 w4 = make_float4(0.f,0.f,0.f,0.f), x4 = make_float4(0.f,0.f,0.f,0.f);
        if (k < S) {
            w4 = *(const float4*)&We[(size_t)k * 64 + col4];
            x4 = *(const float4*)&g_xagg[(size_t)k * 64 + col4];
        }
        *(float4*)&SB[row * 64 + col4] = x4;
        *(float4*)&SB[2048 + row * 64 + col4] = w4;
    }
    __syncthreads();

    int cur = 0;
    for (int kk = 16; kk <= ZCHUNK; kk += 16) {
        float4 nw = make_float4(0.f,0.f,0.f,0.f), nx = make_float4(0.f,0.f,0.f,0.f);
        if (kk < ZCHUNK) {
            int k = k0 + kk + row;
            if (k < S) {
                nw = *(const float4*)&We[(size_t)k * 64 + col4];
                nx = *(const float4*)&g_xagg[(size_t)k * 64 + col4];
            }
        }
        const float* xb = SB + cur * 1024 + kg * 256;          // this group's 4 k-rows
        const float* wb = SB + 2048 + cur * 1024 + kg * 256;
        #pragma unroll
        for (int ks = 0; ks < 4; ks++) {
            ulonglong2 xa = *(const ulonglong2*)&xb[ks * 64 + tb];
            ulonglong2 xc = *(const ulonglong2*)&xb[ks * 64 + tb + 4];
            unsigned long long xs[4] = {xa.x, xa.y, xc.x, xc.y};
            float4 w0 = *(const float4*)&wb[ks * 64 + tl];
            float4 w1 = *(const float4*)&wb[ks * 64 + tl + 4];
            float wsc[8] = {w0.x, w0.y, w0.z, w0.w, w1.x, w1.y, w1.z, w1.w};
            unsigned long long wpk[8];
            #pragma unroll
            for (int j = 0; j < 8; j++) PACKB(wpk[j], wsc[j]);
            #pragma unroll
            for (int p = 0; p < 4; p++)
                #pragma unroll
                for (int j = 0; j < 8; j++)
                    FMA2(acc[p][j], xs[p], wpk[j]);
        }
        if (kk < ZCHUNK) {
            *(float4*)&SB[(cur ^ 1) * 1024 + row * 64 + col4] = nx;
            *(float4*)&SB[2048 + (cur ^ 1) * 1024 + row * 64 + col4] = nw;
        }
        __syncthreads();
        cur ^= 1;
    }

    // 4-phase K-split reduction into SB[l*64 + b]
    for (int g = 0; g < 4; g++) {
        if (kg == g) {
            #pragma unroll
            for (int j = 0; j < 8; j++)
                #pragma unroll
                for (int p = 0; p < 4; p++) {
                    float lo, hi;
                    UNPACK2(lo, hi, acc[p][j]);
                    int base = (tl + j) * 64 + tb + 2 * p;
                    if (g == 0) { SB[base] = lo; SB[base + 1] = hi; }
                    else        { SB[base] += lo; SB[base + 1] += hi; }
                }
        }
        __syncthreads();
    }
    // atomic flush: 16 cells per thread
    int base = tid * 16;
    #pragma unroll
    for (int i = 0; i < 16; i += 4) {
        float4 v = *(const float4*)&SB[base + i];
        atomicAdd(&g_z[base + i],     v.x);
        atomicAdd(&g_z[base + i + 1], v.y);
        atomicAdd(&g_z[base + i + 2], v.z);
        atomicAdd(&g_z[base + i + 3], v.w);
    }
}

// ---------------- y = z @ Wd: 256-m tiles, 8x8 per thread, FFMA2 ----------------
__global__ void __launch_bounds__(256) k_y1(const float* __restrict__ Wd, int S) {
    __shared__ __align__(16) float zz[4096];
    int tid = threadIdx.x;
    int m0 = blockIdx.x * 256;
    #pragma unroll
    for (int pass = 0; pass < 4; pass++) {
        int i = pass * 1024 + tid * 4;
        *(float4*)&zz[i] = *(const float4*)&g_z[i];
    }
    __syncthreads();

    int tb = (tid & 7) * 8;        // b-octet
    int tm = (tid >> 3) * 8;       // m-octet within tile
    int mbase = m0 + tm;
    bool valid = mbase < S;        // S % 8 == 0 -> octet all-or-nothing

    unsigned long long acc[8][4];  // [mi][b-pair]
    #pragma unroll
    for (int mi = 0; mi < 8; mi++)
        #pragma unroll
        for (int p = 0; p < 4; p++) acc[mi][p] = 0ULL;

    #pragma unroll 8
    for (int l = 0; l < 64; l++) {
        ulonglong2 za = *(const ulonglong2*)&zz[l * 64 + tb];
        ulonglong2 zc = *(const ulonglong2*)&zz[l * 64 + tb + 4];
        unsigned long long zp[4] = {za.x, za.y, zc.x, zc.y};
        float4 w0 = make_float4(0.f,0.f,0.f,0.f), w1 = make_float4(0.f,0.f,0.f,0.f);
        if (valid) {
            w0 = *(const float4*)&Wd[(size_t)l * S + mbase];
            w1 = *(const float4*)&Wd[(size_t)l * S + mbase + 4];
        }
        float wsc[8] = {w0.x, w0.y, w0.z, w0.w, w1.x, w1.y, w1.z, w1.w};
        #pragma unroll
        for (int mi = 0; mi < 8; mi++) {
            unsigned long long wpk;
            PACKB(wpk, wsc[mi]);
            #pragma unroll
            for (int p = 0; p < 4; p++)
                FMA2(acc[mi][p], wpk, zp[p]);
        }
    }

    if (valid) {
        #pragma unroll
        for (int mi = 0; mi < 8; mi++) {
            size_t off = (size_t)(mbase + mi) * 64 + tb;
            ulonglong2 v0; v0.x = acc[mi][0]; v0.y = acc[mi][1];
            ulonglong2 v1; v1.x = acc[mi][2]; v1.y = acc[mi][3];
            *(ulonglong2*)&g_yT[off] = v0;
            *(ulonglong2*)&g_yT[off + 4] = v1;
        }
    }
}

// ---------------- finalize: CSR gather, scale, bias, transpose-store ----------------
__global__ void __launch_bounds__(256) k_y2(float* __restrict__ out,
                                            const float* __restrict__ bd,
                                            const int* __restrict__ nn_n, int N) {
    __shared__ float t[64][65];
    int n0 = blockIdx.x * 64;
    int tid = threadIdx.x;
    int r = tid >> 2;               // n within tile 0..63
    int q = (tid & 3) * 16;         // 16 b-columns per thread
    int n = n0 + r;
    if (n < N) {
        int a = g_added[n];
        int mstar = nn_n[n];
        int cnt = g_cnt[n];
        float dn = (float)(cnt + a);
        if (dn < 1.f) dn = 1.f;
        float inv = 1.0f / dn;
        float bdn = (g_bdacc[n] + (a ? bd[mstar] : 0.f)) * inv;

        float acc[16];
        #pragma unroll
        for (int j = 0; j < 16; j++) acc[j] = 0.f;

        int o = g_offY[n];
        for (int s = 0; s < cnt; s++) {
            int m = g_idxY[o + s];
            const float* yr = g_yT + (size_t)m * 64 + q;
            #pragma unroll
            for (int j = 0; j < 16; j += 4) {
                float4 v = *(const float4*)(yr + j);
                acc[j] += v.x; acc[j + 1] += v.y; acc[j + 2] += v.z; acc[j + 3] += v.w;
            }
        }
        if (a) {
            const float* yr = g_yT + (size_t)mstar * 64 + q;
            #pragma unroll
            for (int j = 0; j < 16; j += 4) {
                float4 v = *(const float4*)(yr + j);
                acc[j] += v.x; acc[j + 1] += v.y; acc[j + 2] += v.z; acc[j + 3] += v.w;
            }
        }
        #pragma unroll
        for (int j = 0; j < 16; j++) t[r][q + j] = acc[j] * inv + bdn;
    }
    __syncthreads();
    int cidx = tid & 63;
    if (n0 + cidx < N) {
        #pragma unroll
        for (int b = tid >> 6; b < 64; b += 4)
            out[(size_t)b * N + n0 + cidx] = t[cidx][b];
    }
}

extern "C" void kernel_launch(void* const* d_in, const int* in_sizes, int n_in,
                              void* d_out, int out_size) {
    const float* We   = (const float*)d_in[0];
    const float* be   = (const float*)d_in[1];
    const float* Wd   = (const float*)d_in[2];
    const float* bd   = (const float*)d_in[3];
    const float* x    = (const float*)d_in[4];
    const int*   nn_n = (const int*)d_in[5];
    const int*   nn_m = (const int*)d_in[6];
    int S = in_sizes[3];   // bd_m has S elements
    int N = in_sizes[5];   // nn_n has N elements
    float* out = (float*)d_out;

    int mx = (N > S) ? N : S;
    int cA = (S + 255) / 256;
    int cB = (N + 255) / 256;

    k_prep<<<(mx + 255) / 256, 256>>>(be, S, N);
    k_stats<<<(mx + 255) / 256, 256>>>(nn_n, nn_m, bd, S, N);

    dim3 tb(32, 8);
    dim3 tg((N + 31) / 32, 2);
    k_xT<<<tg, tb>>>(x, N);

    k_scan1<<<cA + cB, 256>>>(S, N, cA);
    k_scan2<<<2, 1024>>>(cA, cB);
    k_scan3<<<cA + cB, 256>>>(S, N, cA);
    k_fill<<<(mx + 255) / 256, 256>>>(nn_n, nn_m, S, N);

    k_xagg<<<(S * 32 + 255) / 256, 256>>>(nn_m, S);
    k_z<<<(S + ZCHUNK - 1) / ZCHUNK, 256>>>(We, S);
    k_y1<<<(S + 255) / 256, 256>>>(Wd, S);
    k_y2<<<(N + 63) / 64, 256>>>(out, bd, nn_n, N);
}

// round 6
// speedup vs baseline: 1.0445x; 1.0445x over previous
#include <cuda_runtime.h>

#define S_MAX 200000
#define N_MAX 250000
#define LB 64           // L == B == 64
#define ZCHUNK 512

// ---- device scratch (no allocations allowed) ----
__device__ float g_xT[(size_t)N_MAX * LB];    // x transposed [N,64]
__device__ float g_xagg[(size_t)S_MAX * LB];  // aggregated+scaled x per master [S,64]
__device__ float g_yT[(size_t)S_MAX * LB];    // y transposed [S,64]
__device__ float g_z[LB * LB];                // z stored l-major: z[l][b]
__device__ int   g_cm[S_MAX];                 // # added new nodes per master
__device__ int   g_cnt[N_MAX];                // # masters mapping to n
__device__ float g_bdacc[N_MAX];              // segment sum of bd_m
__device__ unsigned char g_added[N_MAX];
// CSR A: master m -> added new nodes n
__device__ int   g_offA[S_MAX];
__device__ int   g_fillA[S_MAX];
__device__ int   g_idxA[N_MAX];
// CSR Y: new node n -> masters m
__device__ int   g_offY[N_MAX];
__device__ int   g_fillY[N_MAX];
__device__ int   g_idxY[S_MAX];
// scan temporaries
__device__ int   g_bsumA[1024];
__device__ int   g_boffA[1024];
__device__ int   g_bsumB[1024];
__device__ int   g_boffB[1024];

// ---- streams/events for graph-level concurrency (created pre-capture) ----
static cudaStream_t s2, s3;
static cudaEvent_t evRoot, evStats, evXT, evFY;
namespace {
struct InitStreams {
    InitStreams() {
        cudaStreamCreateWithFlags(&s2, cudaStreamNonBlocking);
        cudaStreamCreateWithFlags(&s3, cudaStreamNonBlocking);
        cudaEventCreateWithFlags(&evRoot, cudaEventDisableTiming);
        cudaEventCreateWithFlags(&evStats, cudaEventDisableTiming);
        cudaEventCreateWithFlags(&evXT, cudaEventDisableTiming);
        cudaEventCreateWithFlags(&evFY, cudaEventDisableTiming);
    }
} s_init;
}

// ---------------- prep: clear everything + z bias ----------------
__global__ void k_prep(const float* __restrict__ be, int S, int N) {
    int i = blockIdx.x * blockDim.x + threadIdx.x;
    if (i < S) { g_cm[i] = 0; g_fillA[i] = 0; }
    if (i < N) { g_cnt[i] = 0; g_bdacc[i] = 0.f; g_fillY[i] = 0; }
    if (i < LB * LB) g_z[i] = be[i >> 6];     // z[l][b] = be[l]
}

// ---------------- stats: added flags + c_m + cnt + bdacc ----------------
__global__ void k_stats(const int* __restrict__ nn_n, const int* __restrict__ nn_m,
                        const float* __restrict__ bd, int S, int N) {
    int i = blockIdx.x * blockDim.x + threadIdx.x;
    if (i < N) {
        int m = nn_n[i];
        int a = (nn_m[m] != i) ? 1 : 0;
        g_added[i] = (unsigned char)a;
        if (a) atomicAdd(&g_cm[m], 1);
    }
    if (i < S) {
        int nm = nn_m[i];
        atomicAdd(&g_cnt[nm], 1);
        atomicAdd(&g_bdacc[nm], bd[i]);
    }
}

// ---------------- x transpose [64,N] -> [N,64] ----------------
__global__ void k_xT(const float* __restrict__ x, int N) {
    __shared__ float tile[32][33];
    int n0 = blockIdx.x * 32;
    int b0 = blockIdx.y * 32;
    int tx = threadIdx.x, ty = threadIdx.y;   // 32 x 8
    #pragma unroll
    for (int i = 0; i < 32; i += 8) {
        int n = n0 + tx;
        tile[ty + i][tx] = (n < N) ? x[(size_t)(b0 + ty + i) * N + n] : 0.f;
    }
    __syncthreads();
    #pragma unroll
    for (int i = 0; i < 32; i += 8) {
        int n = n0 + ty + i;
        if (n < N) g_xT[(size_t)n * LB + b0 + tx] = tile[tx][ty + i];
    }
}

// ---------------- exclusive scans: A chain (cm over S), B chain (cnt over N) ----------------
__global__ void k_scan1A(int S) {
    __shared__ int sd[256];
    int t = threadIdx.x;
    int n = blockIdx.x * 256 + t;
    sd[t] = (n < S) ? g_cm[n] : 0;
    __syncthreads();
    #pragma unroll
    for (int d = 128; d > 0; d >>= 1) { if (t < d) sd[t] += sd[t + d]; __syncthreads(); }
    if (t == 0) g_bsumA[blockIdx.x] = sd[0];
}
__global__ void k_scan1B(int N) {
    __shared__ int sd[256];
    int t = threadIdx.x;
    int n = blockIdx.x * 256 + t;
    sd[t] = (n < N) ? g_cnt[n] : 0;
    __syncthreads();
    #pragma unroll
    for (int d = 128; d > 0; d >>= 1) { if (t < d) sd[t] += sd[t + d]; __syncthreads(); }
    if (t == 0) g_bsumB[blockIdx.x] = sd[0];
}
__global__ void k_scan2A(int nch) {
    __shared__ int sd[1024];
    int t = threadIdx.x;
    int v = (t < nch) ? g_bsumA[t] : 0;
    sd[t] = v;
    __syncthreads();
    #pragma unroll
    for (int d = 1; d < 1024; d <<= 1) {
        int add = (t >= d) ? sd[t - d] : 0;
        __syncthreads(); sd[t] += add; __syncthreads();
    }
    if (t < nch) g_boffA[t] = sd[t] - v;
}
__global__ void k_scan2B(int nch) {
    __shared__ int sd[1024];
    int t = threadIdx.x;
    int v = (t < nch) ? g_bsumB[t] : 0;
    sd[t] = v;
    __syncthreads();
    #pragma unroll
    for (int d = 1; d < 1024; d <<= 1) {
        int add = (t >= d) ? sd[t - d] : 0;
        __syncthreads(); sd[t] += add; __syncthreads();
    }
    if (t < nch) g_boffB[t] = sd[t] - v;
}
__global__ void k_scan3A(int S) {
    __shared__ int sd[256];
    int t = threadIdx.x;
    int n = blockIdx.x * 256 + t;
    int v = (n < S) ? g_cm[n] : 0;
    sd[t] = v;
    __syncthreads();
    #pragma unroll
    for (int d = 1; d < 256; d <<= 1) {
        int add = (t >= d) ? sd[t - d] : 0;
        __syncthreads(); sd[t] += add; __syncthreads();
    }
    if (n < S) g_offA[n] = g_boffA[blockIdx.x] + sd[t] - v;
}
__global__ void k_scan3B(int N) {
    __shared__ int sd[256];
    int t = threadIdx.x;
    int n = blockIdx.x * 256 + t;
    int v = (n < N) ? g_cnt[n] : 0;
    sd[t] = v;
    __syncthreads();
    #pragma unroll
    for (int d = 1; d < 256; d <<= 1) {
        int add = (t >= d) ? sd[t - d] : 0;
        __syncthreads(); sd[t] += add; __syncthreads();
    }
    if (n < N) g_offY[n] = g_boffB[blockIdx.x] + sd[t] - v;
}

// ---------------- CSR index fills ----------------
__global__ void k_fillA(const int* __restrict__ nn_n, int N) {
    int i = blockIdx.x * blockDim.x + threadIdx.x;
    if (i < N && g_added[i]) {
        int m = nn_n[i];
        int pos = g_offA[m] + atomicAdd(&g_fillA[m], 1);
        g_idxA[pos] = i;
    }
}
__global__ void k_fillY(const int* __restrict__ nn_m, int S) {
    int i = blockIdx.x * blockDim.x + threadIdx.x;
    if (i < S) {
        int nm = nn_m[i];
        int pos = g_offY[nm] + atomicAdd(&g_fillY[nm], 1);
        g_idxY[pos] = i;
    }
}

// ---------------- Xagg: half-warp per CSR entry, float4 lanes ----------------
__global__ void __launch_bounds__(256) k_xagg(const int* __restrict__ nn_m, int S) {
    int w = (blockIdx.x * blockDim.x + threadIdx.x) >> 5;
    int lane = threadIdx.x & 31;
    if (w >= S) return;
    int h = lane >> 4;          // half-warp id
    int l16 = lane & 15;        // 16B segment within row
    int cm = g_cm[w];
    float scale = 1.0f / (float)(cm + 1);
    float4 acc = make_float4(0.f, 0.f, 0.f, 0.f);
    if (h == 0)
        acc = *(const float4*)&g_xT[(size_t)nn_m[w] * 64 + l16 * 4];
    int o = g_offA[w];
    for (int s = h; s < cm; s += 2) {
        int n = g_idxA[o + s];
        float4 v = *(const float4*)&g_xT[(size_t)n * 64 + l16 * 4];
        acc.x += v.x; acc.y += v.y; acc.z += v.z; acc.w += v.w;
    }
    acc.x += __shfl_xor_sync(0xffffffffu, acc.x, 16);
    acc.y += __shfl_xor_sync(0xffffffffu, acc.y, 16);
    acc.z += __shfl_xor_sync(0xffffffffu, acc.z, 16);
    acc.w += __shfl_xor_sync(0xffffffffu, acc.w, 16);
    if (h == 0) {
        acc.x *= scale; acc.y *= scale; acc.z *= scale; acc.w *= scale;
        *(float4*)&g_xagg[(size_t)w * 64 + l16 * 4] = acc;
    }
}

// ---------------- z GEMM (round-4 streaming form) ----------------
__global__ void __launch_bounds__(256) k_z(const float* __restrict__ We, int S) {
    __shared__ float sx[2][16][64];
    __shared__ float sw[2][16][64];
    int tid = threadIdx.x;
    int tx = tid & 15, ty = tid >> 4;
    int row = tid >> 4;
    int col4 = (tid & 15) * 4;
    float acc[4][4];
    #pragma unroll
    for (int i = 0; i < 4; i++)
        #pragma unroll
        for (int j = 0; j < 4; j++) acc[i][j] = 0.f;

    int k0 = blockIdx.x * ZCHUNK;
    {
        int k = k0 + row;
        float4 w4 = make_float4(0.f,0.f,0.f,0.f), x4 = make_float4(0.f,0.f,0.f,0.f);
        if (k < S) {
            w4 = *(const float4*)&We[(size_t)k * 64 + col4];
            x4 = *(const float4*)&g_xagg[(size_t)k * 64 + col4];
        }
        *(float4*)&sw[0][row][col4] = w4;
        *(float4*)&sx[0][row][col4] = x4;
    }
    __syncthreads();

    int cur = 0;
    for (int kk = 16; kk <= ZCHUNK; kk += 16) {
        float4 nw = make_float4(0.f,0.f,0.f,0.f), nx = make_float4(0.f,0.f,0.f,0.f);
        if (kk < ZCHUNK) {
            int k = k0 + kk + row;
            if (k < S) {
                nw = *(const float4*)&We[(size_t)k * 64 + col4];
                nx = *(const float4*)&g_xagg[(size_t)k * 64 + col4];
            }
        }
        #pragma unroll
        for (int g = 0; g < 16; g++) {
            float4 xv = *(const float4*)&sx[cur][g][ty * 4];
            float4 wv = *(const float4*)&sw[cur][g][tx * 4];
            acc[0][0] += xv.x * wv.x; acc[0][1] += xv.x * wv.y; acc[0][2] += xv.x * wv.z; acc[0][3] += xv.x * wv.w;
            acc[1][0] += xv.y * wv.x; acc[1][1] += xv.y * wv.y; acc[1][2] += xv.y * wv.z; acc[1][3] += xv.y * wv.w;
            acc[2][0] += xv.z * wv.x; acc[2][1] += xv.z * wv.y; acc[2][2] += xv.z * wv.z; acc[2][3] += xv.z * wv.w;
            acc[3][0] += xv.w * wv.x; acc[3][1] += xv.w * wv.y; acc[3][2] += xv.w * wv.z; acc[3][3] += xv.w * wv.w;
        }
        if (kk < ZCHUNK) {
            *(float4*)&sw[cur ^ 1][row][col4] = nw;
            *(float4*)&sx[cur ^ 1][row][col4] = nx;
        }
        __syncthreads();
        cur ^= 1;
    }

    #pragma unroll
    for (int i = 0; i < 4; i++)
        #pragma unroll
        for (int j = 0; j < 4; j++)
            atomicAdd(&g_z[(tx * 4 + j) * 64 + (ty * 4 + i)], acc[i][j]);
}

// ---------------- y = z @ Wd (round-4 form) ----------------
__global__ void __launch_bounds__(256) k_y1(const float* __restrict__ Wd, int S) {
    __shared__ float sbuf[128 * 68];
    int tid = threadIdx.x;
    int m0 = blockIdx.x * 128;
    for (int i = tid; i < 4096; i += 256) sbuf[i] = g_z[i];
    __syncthreads();

    int tx = tid & 31, ty = tid >> 5;
    int mbase = m0 + tx * 4;
    bool valid = (mbase + 4) <= S;

    float acc[8][4];
    #pragma unroll
    for (int bi = 0; bi < 8; bi++)
        #pragma unroll
        for (int mj = 0; mj < 4; mj++) acc[bi][mj] = 0.f;

    #pragma unroll 4
    for (int l = 0; l < 64; l++) {
        float4 wv = valid ? *(const float4*)&Wd[(size_t)l * S + mbase]
                          : make_float4(0.f, 0.f, 0.f, 0.f);
        float4 z0 = *(const float4*)&sbuf[l * 64 + ty * 8];
        float4 z1 = *(const float4*)&sbuf[l * 64 + ty * 8 + 4];
        float zb[8] = {z0.x, z0.y, z0.z, z0.w, z1.x, z1.y, z1.z, z1.w};
        #pragma unroll
        for (int bi = 0; bi < 8; bi++) {
            acc[bi][0] += zb[bi] * wv.x;
            acc[bi][1] += zb[bi] * wv.y;
            acc[bi][2] += zb[bi] * wv.z;
            acc[bi][3] += zb[bi] * wv.w;
        }
    }
    __syncthreads();

    #pragma unroll
    for (int bi = 0; bi < 8; bi++)
        #pragma unroll
        for (int mj = 0; mj < 4; mj++)
            sbuf[(tx * 4 + mj) * 68 + (ty * 8 + bi)] = acc[bi][mj];
    __syncthreads();

    int cr = tid >> 4;
    int cc = (tid & 15) * 4;
    for (int rr = cr; rr < 128; rr += 16) {
        int m = m0 + rr;
        if (m < S)
            *(float4*)&g_yT[(size_t)m * 64 + cc] = *(const float4*)&sbuf[rr * 68 + cc];
    }
}

// ---------------- finalize: 8 threads/n CSR gather, scale, bias, transpose-store ----------------
__global__ void __launch_bounds__(256) k_y2(float* __restrict__ out,
                                            const float* __restrict__ bd,
                                            const int* __restrict__ nn_n, int N) {
    __shared__ float t[32][65];
    int n0 = blockIdx.x * 32;
    int tid = threadIdx.x;
    int r = tid >> 3;               // n within tile 0..31
    int q = (tid & 7) * 8;          // 8 b-columns per thread
    int n = n0 + r;
    if (n < N) {
        int a = g_added[n];
        int mstar = nn_n[n];
        int cnt = g_cnt[n];
        float dn = (float)(cnt + a);
        if (dn < 1.f) dn = 1.f;
        float inv = 1.0f / dn;
        float bdn = (g_bdacc[n] + (a ? bd[mstar] : 0.f)) * inv;

        float acc[8];
        #pragma unroll
        for (int j = 0; j < 8; j++) acc[j] = 0.f;

        int o = g_offY[n];
        for (int s = 0; s < cnt; s++) {
            int m = g_idxY[o + s];
            const float* yr = g_yT + (size_t)m * 64 + q;
            float4 v0 = *(const float4*)(yr);
            float4 v1 = *(const float4*)(yr + 4);
            acc[0] += v0.x; acc[1] += v0.y; acc[2] += v0.z; acc[3] += v0.w;
            acc[4] += v1.x; acc[5] += v1.y; acc[6] += v1.z; acc[7] += v1.w;
        }
        if (a) {
            const float* yr = g_yT + (size_t)mstar * 64 + q;
            float4 v0 = *(const float4*)(yr);
            float4 v1 = *(const float4*)(yr + 4);
            acc[0] += v0.x; acc[1] += v0.y; acc[2] += v0.z; acc[3] += v0.w;
            acc[4] += v1.x; acc[5] += v1.y; acc[6] += v1.z; acc[7] += v1.w;
        }
        #pragma unroll
        for (int j = 0; j < 8; j++) t[r][q + j] = acc[j] * inv + bdn;
    }
    __syncthreads();
    int cidx = tid & 31;
    if (n0 + cidx < N) {
        #pragma unroll
        for (int b = tid >> 5; b < 64; b += 8)
            out[(size_t)b * N + n0 + cidx] = t[cidx][b];
    }
}

extern "C" void kernel_launch(void* const* d_in, const int* in_sizes, int n_in,
                              void* d_out, int out_size) {
    const float* We   = (const float*)d_in[0];
    const float* be   = (const float*)d_in[1];
    const float* Wd   = (const float*)d_in[2];
    const float* bd   = (const float*)d_in[3];
    const float* x    = (const float*)d_in[4];
    const int*   nn_n = (const int*)d_in[5];
    const int*   nn_m = (const int*)d_in[6];
    int S = in_sizes[3];   // bd_m has S elements
    int N = in_sizes[5];   // nn_n has N elements
    float* out = (float*)d_out;

    int mx = (N > S) ? N : S;
    int cA = (S + 255) / 256;
    int cB = (N + 255) / 256;

    // fork: xT on s2 (depends only on x)
    cudaEventRecord(evRoot, 0);
    cudaStreamWaitEvent(s2, evRoot, 0);
    {
        dim3 tb(32, 8);
        dim3 tg((N + 31) / 32, 2);
        k_xT<<<tg, tb, 0, s2>>>(x, N);
    }
    cudaEventRecord(evXT, s2);

    // main chain: prep -> stats
    k_prep<<<(mx + 255) / 256, 256>>>(be, S, N);
    k_stats<<<(mx + 255) / 256, 256>>>(nn_n, nn_m, bd, S, N);
    cudaEventRecord(evStats, 0);

    // side chain on s3: CSR-Y build (only needed by k_y2)
    cudaStreamWaitEvent(s3, evStats, 0);
    k_scan1B<<<cB, 256, 0, s3>>>(N);
    k_scan2B<<<1, 1024, 0, s3>>>(cB);
    k_scan3B<<<cB, 256, 0, s3>>>(N);
    k_fillY<<<(S + 255) / 256, 256, 0, s3>>>(nn_m, S);
    cudaEventRecord(evFY, s3);

    // main chain: CSR-A build -> xagg -> z -> y1
    k_scan1A<<<cA, 256>>>(S);
    k_scan2A<<<1, 1024>>>(cA);
    k_scan3A<<<cA, 256>>>(S);
    k_fillA<<<(N + 255) / 256, 256>>>(nn_n, N);

    cudaStreamWaitEvent(0, evXT, 0);
    k_xagg<<<(S * 32 + 255) / 256, 256>>>(nn_m, S);
    k_z<<<(S + ZCHUNK - 1) / ZCHUNK, 256>>>(We, S);
    k_y1<<<(S + 127) / 128, 256>>>(Wd, S);

    cudaStreamWaitEvent(0, evFY, 0);
    k_y2<<<(N + 31) / 32, 256>>>(out, bd, nn_n, N);
}